// round 1
// baseline (speedup 1.0000x reference)
#include <cuda_runtime.h>
#include <cuda_bf16.h>
#include <cuda_fp8.h>
#include <mma.h>

using namespace nvcuda;

// Problem shape (fixed by the dataset)
#define M_TOT 32768
#define K_TOT 1024
#define N_TOT 1024
#define NB    8      // K blocks of 128
#define BSQ   128    // quant block size

// ---------------- scratch (static __device__, no allocations) ----------------
__device__ __nv_bfloat16 g_x1[(size_t)M_TOT * K_TOT];  // hi split of quantized x
__device__ __nv_bfloat16 g_x2[(size_t)M_TOT * K_TOT];  // lo split
__device__ __nv_bfloat16 g_w1[(size_t)N_TOT * K_TOT];  // hi split of dual-quant w
__device__ __nv_bfloat16 g_w2[(size_t)N_TOT * K_TOT];  // lo split

// ---------------- helpers ----------------
__device__ __forceinline__ float warp_max(float v) {
#pragma unroll
    for (int o = 16; o > 0; o >>= 1)
        v = fmaxf(v, __shfl_xor_sync(0xffffffffu, v, o));
    return v;
}

// Exact replication of reference: q = clip(x*scale, +-448) -> e4m3 (RNE, satfinite)
// deq = float(q) / scale   (division, matching jnp)
__device__ __forceinline__ float quant_deq_e4m3(float x, float scale) {
    float q = fminf(fmaxf(x * scale, -448.0f), 448.0f);
    __nv_fp8_storage_t s = __nv_cvt_float_to_fp8(q, __NV_SATFINITE, __NV_E4M3);
    float deq = __half2float(__nv_cvt_fp8_to_halfraw(s, __NV_E4M3));
    return deq / scale;
}

// ---------------- kernel 1: quantize x, split to bf16 hi/lo ----------------
// one warp per (row, 128-block); each lane owns 4 consecutive elements
__global__ void __launch_bounds__(256) quant_x_kernel(const float* __restrict__ x) {
    int wg   = (blockIdx.x * blockDim.x + threadIdx.x) >> 5;
    int lane = threadIdx.x & 31;
    if (wg >= M_TOT * NB) return;
    int row = wg >> 3;
    int kb  = wg & 7;

    size_t base = (size_t)row * K_TOT + kb * BSQ;
    float4 v = ((const float4*)(x + base))[lane];
    float vv[4] = {v.x, v.y, v.z, v.w};

    float amax = fmaxf(fmaxf(fabsf(vv[0]), fabsf(vv[1])),
                       fmaxf(fabsf(vv[2]), fabsf(vv[3])));
    amax = warp_max(amax);
    amax = fmaxf(amax, 1e-12f);
    float scale = 448.0f / amax;

    union { __nv_bfloat16 h[4]; uint2 u; } o1, o2;
#pragma unroll
    for (int j = 0; j < 4; j++) {
        float d  = quant_deq_e4m3(vv[j], scale);
        float h  = __bfloat162float(__float2bfloat16_rn(d));
        o1.h[j] = __float2bfloat16_rn(d);
        o2.h[j] = __float2bfloat16_rn(d - h);
    }
    size_t off = base + (size_t)lane * 4;
    *((uint2*)(g_x1 + off)) = o1.u;
    *((uint2*)(g_x2 + off)) = o2.u;
}

// ---------------- kernel 2: dual-quantize w, split to bf16 hi/lo ----------------
__global__ void __launch_bounds__(256) quant_w_kernel(const float* __restrict__ w) {
    int wg   = (blockIdx.x * blockDim.x + threadIdx.x) >> 5;
    int lane = threadIdx.x & 31;
    if (wg >= N_TOT * NB) return;
    int row = wg >> 3;
    int kb  = wg & 7;

    size_t base = (size_t)row * K_TOT + kb * BSQ;
    float4 v = ((const float4*)(w + base))[lane];
    float vv[4] = {v.x, v.y, v.z, v.w};

    // pass 1: hi component
    float amax = fmaxf(fmaxf(fabsf(vv[0]), fabsf(vv[1])),
                       fmaxf(fabsf(vv[2]), fabsf(vv[3])));
    amax = warp_max(amax);
    amax = fmaxf(amax, 1e-12f);
    float s1 = 448.0f / amax;

    float hi[4], r[4];
#pragma unroll
    for (int j = 0; j < 4; j++) {
        hi[j] = quant_deq_e4m3(vv[j], s1);
        r[j]  = vv[j] - hi[j];
    }

    // pass 2: lo component (quantized residual)
    float amax2 = fmaxf(fmaxf(fabsf(r[0]), fabsf(r[1])),
                        fmaxf(fabsf(r[2]), fabsf(r[3])));
    amax2 = warp_max(amax2);
    amax2 = fmaxf(amax2, 1e-12f);
    float s2 = 448.0f / amax2;

    union { __nv_bfloat16 h[4]; uint2 u; } o1, o2;
#pragma unroll
    for (int j = 0; j < 4; j++) {
        float lo = quant_deq_e4m3(r[j], s2);
        float wq = hi[j] + lo;
        float h  = __bfloat162float(__float2bfloat16_rn(wq));
        o1.h[j] = __float2bfloat16_rn(wq);
        o2.h[j] = __float2bfloat16_rn(wq - h);
    }
    size_t off = base + (size_t)lane * 4;
    *((uint2*)(g_w1 + off)) = o1.u;
    *((uint2*)(g_w2 + off)) = o2.u;
}

// ---------------- kernel 3: GEMM  out = x1*w1 + x1*w2 + x2*w1 + bias ----------------
// CTA tile 128x128, BK=32, 8 warps each computing a 32x64 sub-tile via WMMA bf16.
#define BM 128
#define BN 128
#define BK 32
#define SLD 40   // smem leading dim in elements (80B, multiple of 16B)

__global__ void __launch_bounds__(256) gemm_kernel(const float* __restrict__ bias,
                                                   float* __restrict__ out) {
    extern __shared__ char smem_raw[];
    __nv_bfloat16* sA1 = (__nv_bfloat16*)smem_raw;       // [BM][SLD]
    __nv_bfloat16* sA2 = sA1 + BM * SLD;
    __nv_bfloat16* sB1 = sA2 + BM * SLD;
    __nv_bfloat16* sB2 = sB1 + BN * SLD;
    float* sC = (float*)smem_raw;                        // reused in epilogue [128][128]

    int bm = blockIdx.y;    // 0..255
    int bn = blockIdx.x;    // 0..7
    int tid = threadIdx.x;
    int wid = tid >> 5;
    int warp_m = wid & 3;   // 0..3 -> rows (32 each)
    int warp_n = wid >> 2;  // 0..1 -> cols (64 each)

    wmma::fragment<wmma::accumulator, 16, 16, 16, float> acc[2][4];
#pragma unroll
    for (int i = 0; i < 2; i++)
#pragma unroll
        for (int j = 0; j < 4; j++)
            wmma::fill_fragment(acc[i][j], 0.0f);

    const size_t a_row0 = (size_t)bm * BM;
    const size_t b_row0 = (size_t)bn * BN;

    for (int kt = 0; kt < K_TOT; kt += BK) {
        // ---- load 4 tiles (128 rows x 32 cols bf16 each): 512 uint4 per tile ----
#pragma unroll
        for (int ch = 0; ch < 2; ch++) {
            int idx = tid + ch * 256;           // 0..511
            int r   = idx >> 2;                 // row in tile
            int c4  = idx & 3;                  // which 16B chunk of the 64B row
            size_t ga = (a_row0 + r) * K_TOT + kt;
            size_t gb = (b_row0 + r) * K_TOT + kt;
            ((uint4*)(sA1 + r * SLD))[c4] = ((const uint4*)(g_x1 + ga))[c4];
            ((uint4*)(sA2 + r * SLD))[c4] = ((const uint4*)(g_x2 + ga))[c4];
            ((uint4*)(sB1 + r * SLD))[c4] = ((const uint4*)(g_w1 + gb))[c4];
            ((uint4*)(sB2 + r * SLD))[c4] = ((const uint4*)(g_w2 + gb))[c4];
        }
        __syncthreads();

#pragma unroll
        for (int kk = 0; kk < BK; kk += 16) {
            wmma::fragment<wmma::matrix_a, 16, 16, 16, __nv_bfloat16, wmma::row_major> a1[2], a2[2];
            wmma::fragment<wmma::matrix_b, 16, 16, 16, __nv_bfloat16, wmma::col_major> b1[4], b2[4];
#pragma unroll
            for (int i = 0; i < 2; i++) {
                const __nv_bfloat16* pa = sA1 + (warp_m * 32 + i * 16) * SLD + kk;
                wmma::load_matrix_sync(a1[i], pa, SLD);
                wmma::load_matrix_sync(a2[i], pa + (sA2 - sA1), SLD);
            }
#pragma unroll
            for (int j = 0; j < 4; j++) {
                const __nv_bfloat16* pb = sB1 + (warp_n * 64 + j * 16) * SLD + kk;
                wmma::load_matrix_sync(b1[j], pb, SLD);
                wmma::load_matrix_sync(b2[j], pb + (sB2 - sB1), SLD);
            }
#pragma unroll
            for (int i = 0; i < 2; i++)
#pragma unroll
                for (int j = 0; j < 4; j++) {
                    wmma::mma_sync(acc[i][j], a1[i], b1[j], acc[i][j]);
                    wmma::mma_sync(acc[i][j], a1[i], b2[j], acc[i][j]);
                    wmma::mma_sync(acc[i][j], a2[i], b1[j], acc[i][j]);
                }
        }
        __syncthreads();
    }

    // ---- epilogue: stage to smem, add bias, coalesced fp32 store ----
#pragma unroll
    for (int i = 0; i < 2; i++)
#pragma unroll
        for (int j = 0; j < 4; j++)
            wmma::store_matrix_sync(sC + (warp_m * 32 + i * 16) * BN + warp_n * 64 + j * 16,
                                    acc[i][j], BN, wmma::mem_row_major);
    __syncthreads();

    for (int idx = tid; idx < BM * (BN / 4); idx += 256) {
        int r  = idx >> 5;       // row 0..127
        int c4 = idx & 31;       // float4 index 0..31
        float4 vv = ((float4*)(sC + r * BN))[c4];
        int col = bn * BN + c4 * 4;
        vv.x += bias[col + 0];
        vv.y += bias[col + 1];
        vv.z += bias[col + 2];
        vv.w += bias[col + 3];
        ((float4*)(out + (a_row0 + r) * N_TOT + bn * BN))[c4] = vv;
    }
}

// ---------------- launch ----------------
extern "C" void kernel_launch(void* const* d_in, const int* in_sizes, int n_in,
                              void* d_out, int out_size) {
    const float* x      = (const float*)d_in[0];
    const float* weight = (const float*)d_in[1];
    const float* bias   = (const float*)d_in[2];
    float* out          = (float*)d_out;

    // quantize + split (independent, ordered on same stream — fine)
    {
        int tasks = M_TOT * NB;            // warps
        int blocks = (tasks + 7) / 8;      // 8 warps per 256-thread block
        quant_x_kernel<<<blocks, 256>>>(x);
    }
    {
        int tasks = N_TOT * NB;
        int blocks = (tasks + 7) / 8;
        quant_w_kernel<<<blocks, 256>>>(weight);
    }

    // GEMM
    static bool attr_set = false;
    if (!attr_set) {
        cudaFuncSetAttribute(gemm_kernel, cudaFuncAttributeMaxDynamicSharedMemorySize, 65536);
        attr_set = true;
    }
    dim3 grid(N_TOT / BN, M_TOT / BM);  // (8, 256)
    gemm_kernel<<<grid, 256, 65536>>>(bias, out);
}

// round 3
// speedup vs baseline: 1.1579x; 1.1579x over previous
#include <cuda_runtime.h>
#include <cuda_bf16.h>
#include <cuda_fp8.h>
#include <cstdint>

// Problem shape (fixed by the dataset)
#define M_TOT 32768
#define K_TOT 1024
#define N_TOT 1024
#define NB    8      // number of 128-wide K blocks
#define BSQ   128

// ---------------- scratch (static __device__, no allocations) ----------------
__device__ uint8_t g_xq [(size_t)M_TOT * K_TOT];   // e4m3 quantized x
__device__ uint8_t g_whi[(size_t)N_TOT * K_TOT];   // e4m3 weight hi
__device__ uint8_t g_wlo[(size_t)N_TOT * K_TOT];   // e4m3 weight lo (residual)
__device__ float   g_dx [(size_t)NB * M_TOT];      // [b][m] dequant factor 1/scale
__device__ float   g_dhi[(size_t)NB * N_TOT];      // [b][n]
__device__ float   g_dlo[(size_t)NB * N_TOT];      // [b][n]

// ---------------- PTX helpers ----------------
__device__ __forceinline__ uint32_t smem_u32(const void* p) {
    uint32_t a;
    asm("{ .reg .u64 t; cvta.to.shared.u64 t, %1; cvt.u32.u64 %0, t; }" : "=r"(a) : "l"(p));
    return a;
}
#define CP_ASYNC16(saddr, gptr) \
    asm volatile("cp.async.cg.shared.global [%0], [%1], 16;" :: "r"(saddr), "l"(gptr) : "memory")
#define CP_COMMIT() asm volatile("cp.async.commit_group;" ::: "memory")
#define CP_WAIT(n)  asm volatile("cp.async.wait_group %0;" :: "n"(n) : "memory")

__device__ __forceinline__ uint32_t swz128(uint32_t off) {
    return off ^ ((off >> 3) & 0x70);
}

// fp8 e4m3 MMA: D(16x8,f32) += A(16x32,e4m3) * B(32x8,e4m3)
__device__ __forceinline__ void mma_e4m3(float* c, uint32_t a0, uint32_t a1,
                                         uint32_t a2, uint32_t a3,
                                         uint32_t b0, uint32_t b1) {
    asm volatile(
        "mma.sync.aligned.m16n8k32.row.col.f32.e4m3.e4m3.f32 "
        "{%0,%1,%2,%3}, {%4,%5,%6,%7}, {%8,%9}, {%0,%1,%2,%3};"
        : "+f"(c[0]), "+f"(c[1]), "+f"(c[2]), "+f"(c[3])
        : "r"(a0), "r"(a1), "r"(a2), "r"(a3), "r"(b0), "r"(b1));
}

// ---------------- quant helpers ----------------
__device__ __forceinline__ float warp_max(float v) {
#pragma unroll
    for (int o = 16; o > 0; o >>= 1)
        v = fmaxf(v, __shfl_xor_sync(0xffffffffu, v, o));
    return v;
}
// reference-exact: q = e4m3(clip(x*scale, +-448)) with RNE satfinite
__device__ __forceinline__ uint8_t quant_e4m3(float x, float scale) {
    float q = fminf(fmaxf(x * scale, -448.0f), 448.0f);
    return (uint8_t)__nv_cvt_float_to_fp8(q, __NV_SATFINITE, __NV_E4M3);
}
__device__ __forceinline__ float deq_e4m3(uint8_t s, float scale) {
    return __half2float(__nv_cvt_fp8_to_halfraw((__nv_fp8_storage_t)s, __NV_E4M3)) / scale;
}

// ---------------- kernel 1: quantize x -> e4m3 + 1/scale ----------------
// one warp per (row, 128-block); each lane owns 4 consecutive elements
__global__ void __launch_bounds__(256) quant_x_kernel(const float* __restrict__ x) {
    int wg   = (blockIdx.x * blockDim.x + threadIdx.x) >> 5;
    int lane = threadIdx.x & 31;
    if (wg >= M_TOT * NB) return;
    int row = wg >> 3;
    int kb  = wg & 7;

    size_t base = (size_t)row * K_TOT + kb * BSQ;
    float4 v = ((const float4*)(x + base))[lane];
    float vv[4] = {v.x, v.y, v.z, v.w};

    float amax = fmaxf(fmaxf(fabsf(vv[0]), fabsf(vv[1])),
                       fmaxf(fabsf(vv[2]), fabsf(vv[3])));
    amax = fmaxf(warp_max(amax), 1e-12f);
    float scale = 448.0f / amax;

    uint32_t packed = 0;
#pragma unroll
    for (int j = 0; j < 4; j++)
        packed |= (uint32_t)quant_e4m3(vv[j], scale) << (j * 8);
    *((uint32_t*)(g_xq + base + (size_t)lane * 4)) = packed;
    if (lane == 0) g_dx[(size_t)kb * M_TOT + row] = 1.0f / scale;
}

// ---------------- kernel 2: dual-quantize w -> hi/lo e4m3 + scales ----------------
__global__ void __launch_bounds__(256) quant_w_kernel(const float* __restrict__ w) {
    int wg   = (blockIdx.x * blockDim.x + threadIdx.x) >> 5;
    int lane = threadIdx.x & 31;
    if (wg >= N_TOT * NB) return;
    int row = wg >> 3;
    int kb  = wg & 7;

    size_t base = (size_t)row * K_TOT + kb * BSQ;
    float4 v = ((const float4*)(w + base))[lane];
    float vv[4] = {v.x, v.y, v.z, v.w};

    float amax = fmaxf(fmaxf(fabsf(vv[0]), fabsf(vv[1])),
                       fmaxf(fabsf(vv[2]), fabsf(vv[3])));
    amax = fmaxf(warp_max(amax), 1e-12f);
    float s1 = 448.0f / amax;

    uint8_t qh[4];
    float r[4];
#pragma unroll
    for (int j = 0; j < 4; j++) {
        qh[j] = quant_e4m3(vv[j], s1);
        r[j]  = vv[j] - deq_e4m3(qh[j], s1);   // exact residual (division, like ref)
    }

    float amax2 = fmaxf(fmaxf(fabsf(r[0]), fabsf(r[1])),
                        fmaxf(fabsf(r[2]), fabsf(r[3])));
    amax2 = fmaxf(warp_max(amax2), 1e-12f);
    float s2 = 448.0f / amax2;

    uint32_t ph = 0, pl = 0;
#pragma unroll
    for (int j = 0; j < 4; j++) {
        ph |= (uint32_t)qh[j] << (j * 8);
        pl |= (uint32_t)quant_e4m3(r[j], s2) << (j * 8);
    }
    size_t off = base + (size_t)lane * 4;
    *((uint32_t*)(g_whi + off)) = ph;
    *((uint32_t*)(g_wlo + off)) = pl;
    if (lane == 0) {
        g_dhi[(size_t)kb * N_TOT + row] = 1.0f / s1;
        g_dlo[(size_t)kb * N_TOT + row] = 1.0f / s2;
    }
}

// ---------------- kernel 3: block-scaled FP8 GEMM ----------------
// CTA tile 128x128, 512 threads (16 warps, warp tile 32x32), 3-stage cp.async.
#define BM 128
#define BN 128
#define X_TILE 16384               // 128 rows x 128 B
#define W_TILE 16384
#define STAGE_B (X_TILE + 2 * W_TILE)   // 49152
#define NSTAGE 3
#define SCALE_B (3 * 4 * BM * NB / NB * NB)  // placeholder, computed below
#define SMEM_GEMM (1024 + NSTAGE * STAGE_B + 3 * 4096)  // align slack + stages + scales

__global__ void __launch_bounds__(512, 1)
gemm_kernel(const float* __restrict__ bias, float* __restrict__ out) {
    extern __shared__ char smem_raw[];
    // 1024-align the tile region (swizzle atoms)
    char* tile = smem_raw + ((1024 - ((uintptr_t)smem_raw & 1023)) & 1023);
    const uint32_t tile_u = smem_u32(tile);

    float* dx_s  = (float*)(tile + NSTAGE * STAGE_B);   // [NB][128]
    float* dhi_s = dx_s + NB * BM;                      // [NB][128]
    float* dlo_s = dhi_s + NB * BN;                     // [NB][128]

    const int tid  = threadIdx.x;
    const int lane = tid & 31;
    const int wid  = tid >> 5;
    const int gid  = lane >> 2;   // 0..7
    const int tig  = lane & 3;    // 0..3
    const int wm   = (wid & 3) * 32;
    const int wn   = (wid >> 2) * 32;

    const int bm = blockIdx.y;
    const int bn = blockIdx.x;
    const size_t arow0 = (size_t)bm * BM;
    const size_t brow0 = (size_t)bn * BN;

    // ---- prologue: load all per-block scales for this CTA tile (12 KB) ----
    for (int i = tid; i < NB * BM; i += 512) {
        int b = i >> 7, r = i & 127;
        dx_s[i]  = __ldg(&g_dx [(size_t)b * M_TOT + arow0 + r]);
        dhi_s[i] = __ldg(&g_dhi[(size_t)b * N_TOT + brow0 + r]);
        dlo_s[i] = __ldg(&g_dlo[(size_t)b * N_TOT + brow0 + r]);
    }

    // ---- stage loader: 3072 x 16B chunks per stage, 6 per thread ----
    auto load_stage = [&](int s, int b) {
        uint32_t st = tile_u + s * STAGE_B;
#pragma unroll
        for (int j = 0; j < 6; j++) {
            int idx = tid + j * 512;        // 0..3071
            int t   = idx >> 10;            // 0:X 1:Whi 2:Wlo (const per j)
            int k   = idx & 1023;
            int r   = k >> 3, c = k & 7;
            uint32_t so = st + t * X_TILE + swz128(r * 128 + c * 16);
            const uint8_t* g =
                (t == 0) ? (g_xq  + (arow0 + r) * K_TOT)
              : (t == 1) ? (g_whi + (brow0 + r) * K_TOT)
                         : (g_wlo + (brow0 + r) * K_TOT);
            CP_ASYNC16(so, g + b * BSQ + c * 16);
        }
        CP_COMMIT();
    };

    // master accumulators: [mi][ni][4]
    float acc[2][4][4];
#pragma unroll
    for (int mi = 0; mi < 2; mi++)
#pragma unroll
        for (int ni = 0; ni < 4; ni++)
#pragma unroll
            for (int q = 0; q < 4; q++) acc[mi][ni][q] = 0.0f;

    // prime the pipeline
    load_stage(0, 0);
    load_stage(1, 1);
    load_stage(2, 2);

    for (int b = 0; b < NB; b++) {
        if (b < NB - 2)      CP_WAIT(2);
        else if (b == NB - 2) CP_WAIT(1);
        else                 CP_WAIT(0);
        __syncthreads();

        const char* stg = tile + (b % NSTAGE) * STAGE_B;
        const char* Xs  = stg;

#pragma unroll
        for (int ph = 0; ph < 2; ph++) {
            const char*  Ws  = stg + X_TILE + ph * W_TILE;
            const float* dws = ph ? dlo_s : dhi_s;

            float P[2][4][4];
#pragma unroll
            for (int mi = 0; mi < 2; mi++)
#pragma unroll
                for (int ni = 0; ni < 4; ni++)
#pragma unroll
                    for (int q = 0; q < 4; q++) P[mi][ni][q] = 0.0f;

#pragma unroll
            for (int ks = 0; ks < 4; ks++) {
                uint32_t a[2][4];
#pragma unroll
                for (int mi = 0; mi < 2; mi++) {
                    int r0 = wm + mi * 16 + gid;
                    a[mi][0] = *(const uint32_t*)(Xs + swz128((r0    ) * 128 + ks * 32     ) + tig * 4);
                    a[mi][1] = *(const uint32_t*)(Xs + swz128((r0 + 8) * 128 + ks * 32     ) + tig * 4);
                    a[mi][2] = *(const uint32_t*)(Xs + swz128((r0    ) * 128 + ks * 32 + 16) + tig * 4);
                    a[mi][3] = *(const uint32_t*)(Xs + swz128((r0 + 8) * 128 + ks * 32 + 16) + tig * 4);
                }
#pragma unroll
                for (int ni = 0; ni < 4; ni++) {
                    int c0 = wn + ni * 8 + gid;
                    uint32_t b0 = *(const uint32_t*)(Ws + swz128(c0 * 128 + ks * 32     ) + tig * 4);
                    uint32_t b1 = *(const uint32_t*)(Ws + swz128(c0 * 128 + ks * 32 + 16) + tig * 4);
#pragma unroll
                    for (int mi = 0; mi < 2; mi++)
                        mma_e4m3(P[mi][ni], a[mi][0], a[mi][1], a[mi][2], a[mi][3], b0, b1);
                }
            }

            // rescale partial into master: acc += P * dx[row] * dw[col]
            float rs[2][2];
#pragma unroll
            for (int mi = 0; mi < 2; mi++) {
                rs[mi][0] = dx_s[b * BM + wm + mi * 16 + gid];
                rs[mi][1] = dx_s[b * BM + wm + mi * 16 + gid + 8];
            }
#pragma unroll
            for (int ni = 0; ni < 4; ni++) {
                float cs0 = dws[b * BN + wn + ni * 8 + tig * 2];
                float cs1 = dws[b * BN + wn + ni * 8 + tig * 2 + 1];
#pragma unroll
                for (int mi = 0; mi < 2; mi++) {
                    acc[mi][ni][0] = fmaf(P[mi][ni][0], rs[mi][0] * cs0, acc[mi][ni][0]);
                    acc[mi][ni][1] = fmaf(P[mi][ni][1], rs[mi][0] * cs1, acc[mi][ni][1]);
                    acc[mi][ni][2] = fmaf(P[mi][ni][2], rs[mi][1] * cs0, acc[mi][ni][2]);
                    acc[mi][ni][3] = fmaf(P[mi][ni][3], rs[mi][1] * cs1, acc[mi][ni][3]);
                }
            }
        }

        __syncthreads();
        if (b + NSTAGE < NB) load_stage((b + NSTAGE) % NSTAGE, b + NSTAGE);
    }

    // ---- epilogue: add bias, store float2 ----
#pragma unroll
    for (int mi = 0; mi < 2; mi++) {
#pragma unroll
        for (int h = 0; h < 2; h++) {
            size_t row = arow0 + wm + mi * 16 + gid + h * 8;
#pragma unroll
            for (int ni = 0; ni < 4; ni++) {
                int col = bn * BN + wn + ni * 8 + tig * 2;
                float2 bz = *(const float2*)(bias + col);
                float2 v;
                v.x = acc[mi][ni][h * 2 + 0] + bz.x;
                v.y = acc[mi][ni][h * 2 + 1] + bz.y;
                *(float2*)(out + row * N_TOT + col) = v;
            }
        }
    }
}

// ---------------- launch ----------------
extern "C" void kernel_launch(void* const* d_in, const int* in_sizes, int n_in,
                              void* d_out, int out_size) {
    const float* x      = (const float*)d_in[0];
    const float* weight = (const float*)d_in[1];
    const float* bias   = (const float*)d_in[2];
    float* out          = (float*)d_out;

    {
        int tasks = M_TOT * NB;
        quant_x_kernel<<<(tasks + 7) / 8, 256>>>(x);
    }
    {
        int tasks = N_TOT * NB;
        quant_w_kernel<<<(tasks + 7) / 8, 256>>>(weight);
    }

    const int smem_bytes = 1024 + NSTAGE * STAGE_B + 3 * 4 * NB * BM;  // 160768
    static bool attr_set = false;
    if (!attr_set) {
        cudaFuncSetAttribute(gemm_kernel, cudaFuncAttributeMaxDynamicSharedMemorySize, smem_bytes);
        attr_set = true;
    }
    dim3 grid(N_TOT / BN, M_TOT / BM);   // (8, 256)
    gemm_kernel<<<grid, 512, smem_bytes>>>(bias, out);
}

// round 4
// speedup vs baseline: 1.3551x; 1.1703x over previous
#include <cuda_runtime.h>
#include <cuda_bf16.h>
#include <cuda_fp8.h>
#include <cstdint>

// Problem shape (fixed by the dataset)
#define M_TOT 32768
#define K_TOT 1024
#define N_TOT 1024
#define NB    8      // number of 128-wide K blocks
#define BSQ   128

// ---------------- scratch (static __device__, no allocations) ----------------
__device__ uint8_t g_xq [(size_t)M_TOT * K_TOT];   // e4m3 quantized x
__device__ uint8_t g_whi[(size_t)N_TOT * K_TOT];   // e4m3 weight hi
__device__ uint8_t g_wlo[(size_t)N_TOT * K_TOT];   // e4m3 weight lo (residual)
__device__ float   g_dx [(size_t)NB * M_TOT];      // [b][m] dequant factor 1/scale
__device__ float   g_dhi[(size_t)NB * N_TOT];      // [b][n]
__device__ float   g_dlo[(size_t)NB * N_TOT];      // [b][n]

// ---------------- PTX helpers ----------------
__device__ __forceinline__ uint32_t smem_u32(const void* p) {
    uint32_t a;
    asm("{ .reg .u64 t; cvta.to.shared.u64 t, %1; cvt.u32.u64 %0, t; }" : "=r"(a) : "l"(p));
    return a;
}
#define CP_ASYNC16(saddr, gptr) \
    asm volatile("cp.async.cg.shared.global [%0], [%1], 16;" :: "r"(saddr), "l"(gptr) : "memory")
#define CP_COMMIT() asm volatile("cp.async.commit_group;" ::: "memory")
#define CP_WAIT(n)  asm volatile("cp.async.wait_group %0;" :: "n"(n) : "memory")

__device__ __forceinline__ uint32_t swz128(uint32_t off) {
    return off ^ ((off >> 3) & 0x70);
}

// ldmatrix x4: four 8x8 b16 matrices -> 4 regs/lane
__device__ __forceinline__ void ldsm4(uint32_t* r, uint32_t addr) {
    asm volatile("ldmatrix.sync.aligned.m8n8.x4.shared.b16 {%0,%1,%2,%3}, [%4];"
        : "=r"(r[0]), "=r"(r[1]), "=r"(r[2]), "=r"(r[3]) : "r"(addr));
}

// fp8 e4m3 MMA: D(16x8,f32) += A(16x32,e4m3) * B(32x8,e4m3)
__device__ __forceinline__ void mma_e4m3(float* c, const uint32_t* a,
                                         uint32_t b0, uint32_t b1) {
    asm volatile(
        "mma.sync.aligned.m16n8k32.row.col.f32.e4m3.e4m3.f32 "
        "{%0,%1,%2,%3}, {%4,%5,%6,%7}, {%8,%9}, {%0,%1,%2,%3};"
        : "+f"(c[0]), "+f"(c[1]), "+f"(c[2]), "+f"(c[3])
        : "r"(a[0]), "r"(a[1]), "r"(a[2]), "r"(a[3]), "r"(b0), "r"(b1));
}

// ---------------- quant helpers ----------------
__device__ __forceinline__ float warp_max(float v) {
#pragma unroll
    for (int o = 16; o > 0; o >>= 1)
        v = fmaxf(v, __shfl_xor_sync(0xffffffffu, v, o));
    return v;
}
__device__ __forceinline__ uint8_t quant_e4m3(float x, float scale) {
    float q = fminf(fmaxf(x * scale, -448.0f), 448.0f);
    return (uint8_t)__nv_cvt_float_to_fp8(q, __NV_SATFINITE, __NV_E4M3);
}
__device__ __forceinline__ float deq_e4m3(uint8_t s, float scale) {
    return __half2float(__nv_cvt_fp8_to_halfraw((__nv_fp8_storage_t)s, __NV_E4M3)) / scale;
}

// ---------------- kernel 1: quantize x -> e4m3 + 1/scale ----------------
__global__ void __launch_bounds__(256) quant_x_kernel(const float* __restrict__ x) {
    int wg   = (blockIdx.x * blockDim.x + threadIdx.x) >> 5;
    int lane = threadIdx.x & 31;
    if (wg >= M_TOT * NB) return;
    int row = wg >> 3;
    int kb  = wg & 7;

    size_t base = (size_t)row * K_TOT + kb * BSQ;
    float4 v = ((const float4*)(x + base))[lane];
    float vv[4] = {v.x, v.y, v.z, v.w};

    float amax = fmaxf(fmaxf(fabsf(vv[0]), fabsf(vv[1])),
                       fmaxf(fabsf(vv[2]), fabsf(vv[3])));
    amax = fmaxf(warp_max(amax), 1e-12f);
    float scale = 448.0f / amax;

    uint32_t packed = 0;
#pragma unroll
    for (int j = 0; j < 4; j++)
        packed |= (uint32_t)quant_e4m3(vv[j], scale) << (j * 8);
    *((uint32_t*)(g_xq + base + (size_t)lane * 4)) = packed;
    if (lane == 0) g_dx[(size_t)kb * M_TOT + row] = 1.0f / scale;
}

// ---------------- kernel 2: dual-quantize w -> hi/lo e4m3 + scales ----------------
__global__ void __launch_bounds__(256) quant_w_kernel(const float* __restrict__ w) {
    int wg   = (blockIdx.x * blockDim.x + threadIdx.x) >> 5;
    int lane = threadIdx.x & 31;
    if (wg >= N_TOT * NB) return;
    int row = wg >> 3;
    int kb  = wg & 7;

    size_t base = (size_t)row * K_TOT + kb * BSQ;
    float4 v = ((const float4*)(w + base))[lane];
    float vv[4] = {v.x, v.y, v.z, v.w};

    float amax = fmaxf(fmaxf(fabsf(vv[0]), fabsf(vv[1])),
                       fmaxf(fabsf(vv[2]), fabsf(vv[3])));
    amax = fmaxf(warp_max(amax), 1e-12f);
    float s1 = 448.0f / amax;

    uint8_t qh[4];
    float r[4];
#pragma unroll
    for (int j = 0; j < 4; j++) {
        qh[j] = quant_e4m3(vv[j], s1);
        r[j]  = vv[j] - deq_e4m3(qh[j], s1);
    }

    float amax2 = fmaxf(fmaxf(fabsf(r[0]), fabsf(r[1])),
                        fmaxf(fabsf(r[2]), fabsf(r[3])));
    amax2 = fmaxf(warp_max(amax2), 1e-12f);
    float s2 = 448.0f / amax2;

    uint32_t ph = 0, pl = 0;
#pragma unroll
    for (int j = 0; j < 4; j++) {
        ph |= (uint32_t)qh[j] << (j * 8);
        pl |= (uint32_t)quant_e4m3(r[j], s2) << (j * 8);
    }
    size_t off = base + (size_t)lane * 4;
    *((uint32_t*)(g_whi + off)) = ph;
    *((uint32_t*)(g_wlo + off)) = pl;
    if (lane == 0) {
        g_dhi[(size_t)kb * N_TOT + row] = 1.0f / s1;
        g_dlo[(size_t)kb * N_TOT + row] = 1.0f / s2;
    }
}

// ---------------- kernel 3: block-scaled FP8 GEMM ----------------
// CTA tile 128x128, 512 threads (16 warps, warp tile 32x32).
// 4-stage cp.async pipeline, one __syncthreads per K-block, ldmatrix fragments.
#define BM 128
#define BN 128
#define X_TILE 16384               // 128 rows x 128 B
#define W_TILE 16384
#define STAGE_B (X_TILE + 2 * W_TILE)   // 49152
#define NSTAGE 4
#define SMEM_BYTES (1024 + NSTAGE * STAGE_B + 3 * 4 * NB * BM)   // 209920

__global__ void __launch_bounds__(512, 1)
gemm_kernel(const float* __restrict__ bias, float* __restrict__ out) {
    extern __shared__ char smem_raw[];
    char* tile = smem_raw + ((1024 - ((uintptr_t)smem_raw & 1023)) & 1023);
    const uint32_t tile_u = smem_u32(tile);

    float* dx_s  = (float*)(tile + NSTAGE * STAGE_B);   // [NB][128]
    float* dhi_s = dx_s + NB * BM;
    float* dlo_s = dhi_s + NB * BN;

    const int tid  = threadIdx.x;
    const int lane = tid & 31;
    const int wid  = tid >> 5;
    const int gid  = lane >> 2;
    const int tig  = lane & 3;
    const int wm   = (wid & 3) * 32;
    const int wn   = (wid >> 2) * 32;

    const int bm = blockIdx.y;
    const int bn = blockIdx.x;
    const size_t arow0 = (size_t)bm * BM;
    const size_t brow0 = (size_t)bn * BN;

    // ---- ldmatrix per-lane address constants ----
    // swizzle xor bits depend only on (row & 7) == (lane & 7)
    const uint32_t xorb = (uint32_t)(lane & 7) << 4;
    // A: matrix m = lane>>3: rows += (m&1)*8, k-chunk = (m>>1)*16
    const uint32_t a_row = (uint32_t)(wm + ((lane >> 3) & 1) * 8 + (lane & 7));
    const uint32_t Ka    = ((((uint32_t)lane >> 4) & 1) << 4) ^ xorb;
    // B: matrix m: n-rows += (m>>1)*8, k-chunk = (m&1)*16
    const uint32_t b_row = (uint32_t)(wn + ((lane >> 4) & 1) * 8 + (lane & 7));
    const uint32_t Kb    = ((((uint32_t)lane >> 3) & 1) << 4) ^ xorb;

    // ---- per-block scales into smem ----
    for (int i = tid; i < NB * BM; i += 512) {
        int b = i >> 7, r = i & 127;
        dx_s[i]  = __ldg(&g_dx [(size_t)b * M_TOT + arow0 + r]);
        dhi_s[i] = __ldg(&g_dhi[(size_t)b * N_TOT + brow0 + r]);
        dlo_s[i] = __ldg(&g_dlo[(size_t)b * N_TOT + brow0 + r]);
    }

    // ---- stage loader: 3072 x 16B chunks per stage, 6 per thread ----
    auto load_stage = [&](int s, int b) {
        uint32_t st = tile_u + s * STAGE_B;
#pragma unroll
        for (int j = 0; j < 6; j++) {
            int idx = tid + j * 512;        // 0..3071
            int t   = idx >> 10;            // 0:X 1:Whi 2:Wlo
            int k   = idx & 1023;
            int r   = k >> 3, c = k & 7;
            uint32_t so = st + t * X_TILE + swz128(r * 128 + c * 16);
            const uint8_t* g =
                (t == 0) ? (g_xq  + (arow0 + r) * K_TOT)
              : (t == 1) ? (g_whi + (brow0 + r) * K_TOT)
                         : (g_wlo + (brow0 + r) * K_TOT);
            CP_ASYNC16(so, g + b * BSQ + c * 16);
        }
        CP_COMMIT();
    };

    float acc[2][4][4];
#pragma unroll
    for (int mi = 0; mi < 2; mi++)
#pragma unroll
        for (int ni = 0; ni < 4; ni++)
#pragma unroll
            for (int q = 0; q < 4; q++) acc[mi][ni][q] = 0.0f;

    // prime pipeline: stages 0..2
    load_stage(0, 0);
    load_stage(1, 1);
    load_stage(2, 2);

#pragma unroll 1
    for (int b = 0; b < NB; b++) {
        if (b < NB - 2)       CP_WAIT(2);
        else if (b == NB - 2) CP_WAIT(1);
        else                  CP_WAIT(0);
        __syncthreads();
        if (b + 3 < NB) load_stage((b + 3) & 3, b + 3);

        const uint32_t stg_u = tile_u + (b & 3) * STAGE_B;

#pragma unroll
        for (int ph = 0; ph < 2; ph++) {
            const uint32_t Wu = stg_u + X_TILE + ph * W_TILE;
            const float* dws = ph ? dlo_s : dhi_s;

            float P[2][4][4];
#pragma unroll
            for (int mi = 0; mi < 2; mi++)
#pragma unroll
                for (int ni = 0; ni < 4; ni++)
#pragma unroll
                    for (int q = 0; q < 4; q++) P[mi][ni][q] = 0.0f;

#pragma unroll
            for (int ks = 0; ks < 4; ks++) {
                const uint32_t ka = ((uint32_t)ks * 32) ^ Ka;
                const uint32_t kb2 = ((uint32_t)ks * 32) ^ Kb;
                uint32_t A0[4], A1[4], B0[4], B1[4];
                ldsm4(A0, stg_u + a_row * 128 + ka);
                ldsm4(A1, stg_u + (a_row + 16) * 128 + ka);
                ldsm4(B0, Wu + b_row * 128 + kb2);
                ldsm4(B1, Wu + (b_row + 16) * 128 + kb2);

                mma_e4m3(P[0][0], A0, B0[0], B0[1]);
                mma_e4m3(P[1][0], A1, B0[0], B0[1]);
                mma_e4m3(P[0][1], A0, B0[2], B0[3]);
                mma_e4m3(P[1][1], A1, B0[2], B0[3]);
                mma_e4m3(P[0][2], A0, B1[0], B1[1]);
                mma_e4m3(P[1][2], A1, B1[0], B1[1]);
                mma_e4m3(P[0][3], A0, B1[2], B1[3]);
                mma_e4m3(P[1][3], A1, B1[2], B1[3]);
            }

            // rescale partial into master: acc += P * dx[row] * dw[col]
            float rs[2][2];
#pragma unroll
            for (int mi = 0; mi < 2; mi++) {
                rs[mi][0] = dx_s[b * BM + wm + mi * 16 + gid];
                rs[mi][1] = dx_s[b * BM + wm + mi * 16 + gid + 8];
            }
#pragma unroll
            for (int ni = 0; ni < 4; ni++) {
                float cs0 = dws[b * BN + wn + ni * 8 + tig * 2];
                float cs1 = dws[b * BN + wn + ni * 8 + tig * 2 + 1];
#pragma unroll
                for (int mi = 0; mi < 2; mi++) {
                    acc[mi][ni][0] = fmaf(P[mi][ni][0], rs[mi][0] * cs0, acc[mi][ni][0]);
                    acc[mi][ni][1] = fmaf(P[mi][ni][1], rs[mi][0] * cs1, acc[mi][ni][1]);
                    acc[mi][ni][2] = fmaf(P[mi][ni][2], rs[mi][1] * cs0, acc[mi][ni][2]);
                    acc[mi][ni][3] = fmaf(P[mi][ni][3], rs[mi][1] * cs1, acc[mi][ni][3]);
                }
            }
        }
    }

    // ---- epilogue: add bias, store float2 ----
#pragma unroll
    for (int mi = 0; mi < 2; mi++) {
#pragma unroll
        for (int h = 0; h < 2; h++) {
            size_t row = arow0 + wm + mi * 16 + gid + h * 8;
#pragma unroll
            for (int ni = 0; ni < 4; ni++) {
                int col = bn * BN + wn + ni * 8 + tig * 2;
                float2 bz = *(const float2*)(bias + col);
                float2 v;
                v.x = acc[mi][ni][h * 2 + 0] + bz.x;
                v.y = acc[mi][ni][h * 2 + 1] + bz.y;
                *(float2*)(out + row * N_TOT + col) = v;
            }
        }
    }
}

// ---------------- launch ----------------
extern "C" void kernel_launch(void* const* d_in, const int* in_sizes, int n_in,
                              void* d_out, int out_size) {
    const float* x      = (const float*)d_in[0];
    const float* weight = (const float*)d_in[1];
    const float* bias   = (const float*)d_in[2];
    float* out          = (float*)d_out;

    {
        int tasks = M_TOT * NB;
        quant_x_kernel<<<(tasks + 7) / 8, 256>>>(x);
    }
    {
        int tasks = N_TOT * NB;
        quant_w_kernel<<<(tasks + 7) / 8, 256>>>(weight);
    }

    static bool attr_set = false;
    if (!attr_set) {
        cudaFuncSetAttribute(gemm_kernel, cudaFuncAttributeMaxDynamicSharedMemorySize, SMEM_BYTES);
        attr_set = true;
    }
    dim3 grid(N_TOT / BN, M_TOT / BM);   // (8, 256)
    gemm_kernel<<<grid, 512, SMEM_BYTES>>>(bias, out);
}

// round 5
// speedup vs baseline: 1.9379x; 1.4300x over previous
#include <cuda_runtime.h>
#include <cuda_bf16.h>
#include <cuda_fp8.h>
#include <cstdint>

// Problem shape (fixed by the dataset)
#define M_TOT 32768
#define K_TOT 1024
#define N_TOT 1024
#define NB    8      // number of 128-wide K blocks
#define BSQ   128

// ---------------- scratch (static __device__, no allocations) ----------------
__device__ uint8_t g_xq [(size_t)M_TOT * K_TOT];   // e4m3 quantized x
__device__ uint8_t g_whi[(size_t)N_TOT * K_TOT];   // e4m3 weight hi
__device__ uint8_t g_wlo[(size_t)N_TOT * K_TOT];   // e4m3 weight lo (residual)
__device__ float   g_dx [(size_t)NB * M_TOT];      // [b][m] dequant factor 1/scale
__device__ float   g_dhi[(size_t)NB * N_TOT];      // [b][n]
__device__ float   g_dlo[(size_t)NB * N_TOT];      // [b][n]

// ---------------- PTX helpers ----------------
__device__ __forceinline__ uint32_t smem_u32(const void* p) {
    uint32_t a;
    asm("{ .reg .u64 t; cvta.to.shared.u64 t, %1; cvt.u32.u64 %0, t; }" : "=r"(a) : "l"(p));
    return a;
}
#define CP_ASYNC16(saddr, gptr) \
    asm volatile("cp.async.cg.shared.global [%0], [%1], 16;" :: "r"(saddr), "l"(gptr) : "memory")
#define CP_COMMIT() asm volatile("cp.async.commit_group;" ::: "memory")
#define CP_WAIT(n)  asm volatile("cp.async.wait_group %0;" :: "n"(n) : "memory")

// ldmatrix x4: four 8x8 b16 matrices -> 4 regs/lane
__device__ __forceinline__ void ldsm4(uint32_t* r, uint32_t addr) {
    asm volatile("ldmatrix.sync.aligned.m8n8.x4.shared.b16 {%0,%1,%2,%3}, [%4];"
        : "=r"(r[0]), "=r"(r[1]), "=r"(r[2]), "=r"(r[3]) : "r"(addr));
}

// fp8 e4m3 MMA: D(16x8,f32) += A(16x32,e4m3) * B(32x8,e4m3)
__device__ __forceinline__ void mma_e4m3(float* c, const uint32_t* a,
                                         uint32_t b0, uint32_t b1) {
    asm volatile(
        "mma.sync.aligned.m16n8k32.row.col.f32.e4m3.e4m3.f32 "
        "{%0,%1,%2,%3}, {%4,%5,%6,%7}, {%8,%9}, {%0,%1,%2,%3};"
        : "+f"(c[0]), "+f"(c[1]), "+f"(c[2]), "+f"(c[3])
        : "r"(a[0]), "r"(a[1]), "r"(a[2]), "r"(a[3]), "r"(b0), "r"(b1));
}

// ---------------- quant helpers ----------------
__device__ __forceinline__ float warp_max(float v) {
#pragma unroll
    for (int o = 16; o > 0; o >>= 1)
        v = fmaxf(v, __shfl_xor_sync(0xffffffffu, v, o));
    return v;
}
__device__ __forceinline__ uint8_t quant_e4m3(float x, float scale) {
    float q = fminf(fmaxf(x * scale, -448.0f), 448.0f);
    return (uint8_t)__nv_cvt_float_to_fp8(q, __NV_SATFINITE, __NV_E4M3);
}
__device__ __forceinline__ float deq_e4m3(uint8_t s, float scale) {
    return __half2float(__nv_cvt_fp8_to_halfraw((__nv_fp8_storage_t)s, __NV_E4M3)) / scale;
}
// HW pair conversion: byte0 = f0, byte1 = f1 (satfinite == clip(+-448) + RNE for finite)
__device__ __forceinline__ uint32_t cvt4_e4m3(float f0, float f1, float f2, float f3) {
    uint16_t lo, hi;
    asm("cvt.rn.satfinite.e4m3x2.f32 %0, %1, %2;" : "=h"(lo) : "f"(f1), "f"(f0));
    asm("cvt.rn.satfinite.e4m3x2.f32 %0, %1, %2;" : "=h"(hi) : "f"(f3), "f"(f2));
    return (uint32_t)lo | ((uint32_t)hi << 16);
}

// ---------------- kernel 1: quantize x -> e4m3 + 1/scale ----------------
__global__ void __launch_bounds__(256) quant_x_kernel(const float* __restrict__ x) {
    int wg   = (blockIdx.x * blockDim.x + threadIdx.x) >> 5;
    int lane = threadIdx.x & 31;
    if (wg >= M_TOT * NB) return;
    int row = wg >> 3;
    int kb  = wg & 7;

    size_t base = (size_t)row * K_TOT + kb * BSQ;
    float4 v = ((const float4*)(x + base))[lane];

    float amax = fmaxf(fmaxf(fabsf(v.x), fabsf(v.y)),
                       fmaxf(fabsf(v.z), fabsf(v.w)));
    amax = fmaxf(warp_max(amax), 1e-12f);
    float scale = 448.0f / amax;

    uint32_t packed = cvt4_e4m3(v.x * scale, v.y * scale, v.z * scale, v.w * scale);
    *((uint32_t*)(g_xq + base + (size_t)lane * 4)) = packed;
    if (lane == 0) g_dx[(size_t)kb * M_TOT + row] = 1.0f / scale;
}

// ---------------- kernel 2: dual-quantize w -> hi/lo e4m3 + scales ----------------
__global__ void __launch_bounds__(256) quant_w_kernel(const float* __restrict__ w) {
    int wg   = (blockIdx.x * blockDim.x + threadIdx.x) >> 5;
    int lane = threadIdx.x & 31;
    if (wg >= N_TOT * NB) return;
    int row = wg >> 3;
    int kb  = wg & 7;

    size_t base = (size_t)row * K_TOT + kb * BSQ;
    float4 v = ((const float4*)(w + base))[lane];
    float vv[4] = {v.x, v.y, v.z, v.w};

    float amax = fmaxf(fmaxf(fabsf(vv[0]), fabsf(vv[1])),
                       fmaxf(fabsf(vv[2]), fabsf(vv[3])));
    amax = fmaxf(warp_max(amax), 1e-12f);
    float s1 = 448.0f / amax;

    uint8_t qh[4];
    float r[4];
#pragma unroll
    for (int j = 0; j < 4; j++) {
        qh[j] = quant_e4m3(vv[j], s1);
        r[j]  = vv[j] - deq_e4m3(qh[j], s1);
    }

    float amax2 = fmaxf(fmaxf(fabsf(r[0]), fabsf(r[1])),
                        fmaxf(fabsf(r[2]), fabsf(r[3])));
    amax2 = fmaxf(warp_max(amax2), 1e-12f);
    float s2 = 448.0f / amax2;

    uint32_t ph = 0, pl = 0;
#pragma unroll
    for (int j = 0; j < 4; j++) {
        ph |= (uint32_t)qh[j] << (j * 8);
        pl |= (uint32_t)quant_e4m3(r[j], s2) << (j * 8);
    }
    size_t off = base + (size_t)lane * 4;
    *((uint32_t*)(g_whi + off)) = ph;
    *((uint32_t*)(g_wlo + off)) = pl;
    if (lane == 0) {
        g_dhi[(size_t)kb * N_TOT + row] = 1.0f / s1;
        g_dlo[(size_t)kb * N_TOT + row] = 1.0f / s2;
    }
}

// ---------------- kernel 3: block-scaled FP8 GEMM ----------------
// CTA tile 128(M)x64(N), 256 threads (8 warps, 4x2 grid of 32x32 warp tiles).
// K stepped in 64-wide halves (16 steps), 4-stage cp.async pipeline, SW64 swizzle,
// 2 CTAs/SM.
#define BM 128
#define BN 64
#define NSTEP 16                   // K steps of 64
#define X_TILE 8192                // 128 rows x 64 B
#define W_TILE 4096                // 64 rows x 64 B
#define STAGE_B (X_TILE + 2 * W_TILE)   // 16384
#define NSTAGE 4
#define SCALES_B (4 * (NB * BM + 2 * NB * BN))   // 8192
#define SMEM_BYTES (1024 + NSTAGE * STAGE_B + SCALES_B)  // 74752

__global__ void __launch_bounds__(256, 2)
gemm_kernel(const float* __restrict__ bias, float* __restrict__ out) {
    extern __shared__ char smem_raw[];
    char* tile = smem_raw + ((1024 - ((uintptr_t)smem_raw & 1023)) & 1023);
    const uint32_t tile_u = smem_u32(tile);

    float* dx_s  = (float*)(tile + NSTAGE * STAGE_B);   // [NB][BM]
    float* dhi_s = dx_s + NB * BM;                      // [NB][BN]
    float* dlo_s = dhi_s + NB * BN;

    const int tid  = threadIdx.x;
    const int lane = tid & 31;
    const int wid  = tid >> 5;
    const int gid  = lane >> 2;
    const int tig  = lane & 3;
    const int wm   = (wid & 3) * 32;   // 0..96
    const int wn   = (wid >> 2) * 32;  // 0 or 32

    const int bn = blockIdx.x;   // 0..15
    const int bm = blockIdx.y;   // 0..255
    const size_t arow0 = (size_t)bm * BM;
    const size_t brow0 = (size_t)bn * BN;

    // ---- ldmatrix per-lane constants (SW64: col ^= (row&6)<<3) ----
    const uint32_t arow_l = (uint32_t)(wm + ((lane >> 3) & 1) * 8 + (lane & 7));
    const uint32_t acb    = ((uint32_t)(lane >> 4) & 1) * 16;
    const uint32_t xa     = (arow_l & 6) << 3;
    const uint32_t brow_l = (uint32_t)(wn + ((lane >> 4) & 1) * 8 + (lane & 7));
    const uint32_t bcb    = ((uint32_t)(lane >> 3) & 1) * 16;
    const uint32_t xb     = (brow_l & 6) << 3;

    // ---- per-block scales into smem ----
    for (int i = tid; i < NB * BM; i += 256)
        dx_s[i] = __ldg(&g_dx[(size_t)(i >> 7) * M_TOT + arow0 + (i & 127)]);
    for (int i = tid; i < NB * BN; i += 256) {
        int b = i >> 6, r = i & 63;
        dhi_s[i] = __ldg(&g_dhi[(size_t)b * N_TOT + brow0 + r]);
        dlo_s[i] = __ldg(&g_dlo[(size_t)b * N_TOT + brow0 + r]);
    }

    // ---- stage loader: 1024 x 16B chunks per stage, 4 per thread ----
    auto load_stage = [&](int st_idx, int s) {
        uint32_t st = tile_u + st_idx * STAGE_B;
        int koff = s * 64;
#pragma unroll
        for (int j = 0; j < 2; j++) {          // X: 512 chunks
            int idx = tid + j * 256;
            int r = idx >> 2, c = idx & 3;
            uint32_t so = r * 64 + ((c * 16) ^ ((r & 6) << 3));
            CP_ASYNC16(st + so, g_xq + (arow0 + r) * K_TOT + koff + c * 16);
        }
        {                                       // Whi + Wlo: 256 chunks each
            int r = tid >> 2, c = tid & 3;
            uint32_t so = r * 64 + ((c * 16) ^ ((r & 6) << 3));
            size_t go = (brow0 + r) * K_TOT + koff + c * 16;
            CP_ASYNC16(st + X_TILE + so, g_whi + go);
            CP_ASYNC16(st + X_TILE + W_TILE + so, g_wlo + go);
        }
        CP_COMMIT();
    };

    float acc[2][4][4];
#pragma unroll
    for (int mi = 0; mi < 2; mi++)
#pragma unroll
        for (int ni = 0; ni < 4; ni++)
#pragma unroll
            for (int q = 0; q < 4; q++) acc[mi][ni][q] = 0.0f;

    // prime pipeline
    load_stage(0, 0);
    load_stage(1, 1);
    load_stage(2, 2);

#pragma unroll 1
    for (int s = 0; s < NSTEP; s++) {
        if (s < NSTEP - 2)       CP_WAIT(2);
        else if (s == NSTEP - 2) CP_WAIT(1);
        else                     CP_WAIT(0);
        __syncthreads();
        if (s + 3 < NSTEP) load_stage((s + 3) & 3, s + 3);

        const uint32_t Xu = tile_u + (s & 3) * STAGE_B;
        const int b = s >> 1;

        // A fragments for both k-halves (shared across hi/lo phases)
        uint32_t A[2][2][4];
#pragma unroll
        for (int ks = 0; ks < 2; ks++) {
            uint32_t ca = (acb + ks * 32) ^ xa;
            ldsm4(A[0][ks], Xu + arow_l * 64 + ca);
            ldsm4(A[1][ks], Xu + (arow_l + 16) * 64 + ca);
        }

        // row scales (same for both phases)
        float rs[2][2];
#pragma unroll
        for (int mi = 0; mi < 2; mi++) {
            rs[mi][0] = dx_s[b * BM + wm + mi * 16 + gid];
            rs[mi][1] = dx_s[b * BM + wm + mi * 16 + gid + 8];
        }

#pragma unroll
        for (int ph = 0; ph < 2; ph++) {
            const uint32_t Wu = Xu + X_TILE + ph * W_TILE;
            const float* dws = ph ? dlo_s : dhi_s;

            float P[2][4][4];
#pragma unroll
            for (int mi = 0; mi < 2; mi++)
#pragma unroll
                for (int ni = 0; ni < 4; ni++)
#pragma unroll
                    for (int q = 0; q < 4; q++) P[mi][ni][q] = 0.0f;

#pragma unroll
            for (int ks = 0; ks < 2; ks++) {
                uint32_t cb = (bcb + ks * 32) ^ xb;
                uint32_t B0[4], B1[4];
                ldsm4(B0, Wu + brow_l * 64 + cb);
                ldsm4(B1, Wu + (brow_l + 16) * 64 + cb);

                mma_e4m3(P[0][0], A[0][ks], B0[0], B0[1]);
                mma_e4m3(P[1][0], A[1][ks], B0[0], B0[1]);
                mma_e4m3(P[0][1], A[0][ks], B0[2], B0[3]);
                mma_e4m3(P[1][1], A[1][ks], B0[2], B0[3]);
                mma_e4m3(P[0][2], A[0][ks], B1[0], B1[1]);
                mma_e4m3(P[1][2], A[1][ks], B1[0], B1[1]);
                mma_e4m3(P[0][3], A[0][ks], B1[2], B1[3]);
                mma_e4m3(P[1][3], A[1][ks], B1[2], B1[3]);
            }

            // rescale half-block partial into master
#pragma unroll
            for (int ni = 0; ni < 4; ni++) {
                float cs0 = dws[b * BN + wn + ni * 8 + tig * 2];
                float cs1 = dws[b * BN + wn + ni * 8 + tig * 2 + 1];
#pragma unroll
                for (int mi = 0; mi < 2; mi++) {
                    acc[mi][ni][0] = fmaf(P[mi][ni][0], rs[mi][0] * cs0, acc[mi][ni][0]);
                    acc[mi][ni][1] = fmaf(P[mi][ni][1], rs[mi][0] * cs1, acc[mi][ni][1]);
                    acc[mi][ni][2] = fmaf(P[mi][ni][2], rs[mi][1] * cs0, acc[mi][ni][2]);
                    acc[mi][ni][3] = fmaf(P[mi][ni][3], rs[mi][1] * cs1, acc[mi][ni][3]);
                }
            }
        }
    }

    // ---- epilogue: add bias, store float2 ----
#pragma unroll
    for (int mi = 0; mi < 2; mi++) {
#pragma unroll
        for (int h = 0; h < 2; h++) {
            size_t row = arow0 + wm + mi * 16 + gid + h * 8;
#pragma unroll
            for (int ni = 0; ni < 4; ni++) {
                int col = bn * BN + wn + ni * 8 + tig * 2;
                float2 bz = *(const float2*)(bias + col);
                float2 v;
                v.x = acc[mi][ni][h * 2 + 0] + bz.x;
                v.y = acc[mi][ni][h * 2 + 1] + bz.y;
                *(float2*)(out + row * N_TOT + col) = v;
            }
        }
    }
}

// ---------------- launch ----------------
extern "C" void kernel_launch(void* const* d_in, const int* in_sizes, int n_in,
                              void* d_out, int out_size) {
    const float* x      = (const float*)d_in[0];
    const float* weight = (const float*)d_in[1];
    const float* bias   = (const float*)d_in[2];
    float* out          = (float*)d_out;

    {
        int tasks = M_TOT * NB;
        quant_x_kernel<<<(tasks + 7) / 8, 256>>>(x);
    }
    {
        int tasks = N_TOT * NB;
        quant_w_kernel<<<(tasks + 7) / 8, 256>>>(weight);
    }

    static bool attr_set = false;
    if (!attr_set) {
        cudaFuncSetAttribute(gemm_kernel, cudaFuncAttributeMaxDynamicSharedMemorySize, SMEM_BYTES);
        attr_set = true;
    }
    dim3 grid(N_TOT / BN, M_TOT / BM);   // (16, 256)
    gemm_kernel<<<grid, 256, SMEM_BYTES>>>(bias, out);
}